// round 2
// baseline (speedup 1.0000x reference)
#include <cuda_runtime.h>

#define THREADS 256
#define CONF_BLOCKS 2048

// ---------------------------------------------------------------------------
// Block-level sum reduction: warp shuffle + one shared pass.
// ---------------------------------------------------------------------------
__device__ __forceinline__ float block_reduce_sum(float v) {
    __shared__ float s[32];
    int lane = threadIdx.x & 31;
    int wid  = threadIdx.x >> 5;
#pragma unroll
    for (int o = 16; o > 0; o >>= 1) v += __shfl_down_sync(0xffffffffu, v, o);
    if (lane == 0) s[wid] = v;
    __syncthreads();
    int nwarps = blockDim.x >> 5;
    v = (threadIdx.x < nwarps) ? s[lane] : 0.0f;
    if (wid == 0) {
#pragma unroll
        for (int o = 16; o > 0; o >>= 1) v += __shfl_down_sync(0xffffffffu, v, o);
    }
    __syncthreads();   // safe for reuse by a second call
    return v;
}

// ---------------------------------------------------------------------------
// Zero the 3 output scalars (d_out is poisoned by the harness).
// ---------------------------------------------------------------------------
__global__ void zero_out_kernel(float* out) {
    if (threadIdx.x < 3) out[threadIdx.x] = 0.0f;
}

// ---------------------------------------------------------------------------
// confidence_loss = sum(weight * (conf - conf_gt)^2) / 65536
// 16.78M elements x 3 arrays, float4-vectorized grid-stride reduction.
// Pure HBM-bound: ~201 MB of reads.
// ---------------------------------------------------------------------------
__global__ void conf_loss_kernel(const float4* __restrict__ c,
                                 const float4* __restrict__ g,
                                 const float4* __restrict__ w,
                                 float* __restrict__ out, int n4) {
    float acc = 0.0f;
    for (int i = blockIdx.x * blockDim.x + threadIdx.x; i < n4;
         i += gridDim.x * blockDim.x) {
        float4 cc = __ldg(c + i);
        float4 gg = __ldg(g + i);
        float4 ww = __ldg(w + i);
        float d;
        d = cc.x - gg.x; acc = fmaf(ww.x * d, d, acc);
        d = cc.y - gg.y; acc = fmaf(ww.y * d, d, acc);
        d = cc.z - gg.z; acc = fmaf(ww.z * d, d, acc);
        d = cc.w - gg.w; acc = fmaf(ww.w * d, d, acc);
    }
    acc = block_reduce_sum(acc);
    if (threadIdx.x == 0) atomicAdd(out, acc * (1.0f / 65536.0f));
}

// ---------------------------------------------------------------------------
// quat -> rotation matrix (row-major r[9]), matches reference quat2mat.
// ---------------------------------------------------------------------------
__device__ __forceinline__ void quat2mat(float q0, float q1, float q2, float q3,
                                         float* r) {
    float q00 = q0 * q0, q11 = q1 * q1, q22 = q2 * q2, q33 = q3 * q3;
    r[0] = q00 + q11 - q22 - q33;
    r[1] = 2.0f * (q1 * q2 - q0 * q3);
    r[2] = 2.0f * (q1 * q3 + q0 * q2);
    r[3] = 2.0f * (q1 * q2 + q0 * q3);
    r[4] = q00 - q11 + q22 - q33;
    r[5] = 2.0f * (q2 * q3 - q0 * q1);
    r[6] = 2.0f * (q1 * q3 - q0 * q2);
    r[7] = 2.0f * (q2 * q3 + q0 * q1);
    r[8] = q00 - q11 - q22 + q33;
}

// ---------------------------------------------------------------------------
// depth_loss    = sum(mask * (dr[:,0]-av[:,0])^2) / N          -> out[1]
// rotation_loss = sum(mask * min(n1, n2)) / N                  -> out[2]
//   m_pred = quat2mat(av[:,1:])            (unnormalized!)
//   m_gt   = quat2mat(normalize(dr[:,1:]))
//   n1 = ||m_gt - m_pred||_F
//   n2 = ||m_gt - m_pred @ RY||_F,  RY = diag(-1, 1, -1) (column sign flip)
// NOTE: ann_flags is materialized as int32 by the harness (rel_err 0.763
// fingerprint from reading it as bytes).
// ---------------------------------------------------------------------------
__global__ void ann_loss_kernel(const float* __restrict__ dr,
                                const float* __restrict__ av,
                                const int* __restrict__ flags,
                                float* __restrict__ out, int N) {
    int i = blockIdx.x * blockDim.x + threadIdx.x;
    float dacc = 0.0f, racc = 0.0f;
    if (i < N && flags[i] != 0) {
        const float* dri = dr + 5 * i;
        const float* avi = av + 5 * i;

        float dd = dri[0] - avi[0];
        dacc = dd * dd;

        float mp[9];
        quat2mat(avi[1], avi[2], avi[3], avi[4], mp);

        float q0 = dri[1], q1 = dri[2], q2 = dri[3], q3 = dri[4];
        float inv = 1.0f / sqrtf(q0 * q0 + q1 * q1 + q2 * q2 + q3 * q3);
        float mg[9];
        quat2mat(q0 * inv, q1 * inv, q2 * inv, q3 * inv, mg);

        // RY = diag(-1,1,-1): m_pred @ RY negates columns 0 and 2.
        float s1 = 0.0f, s2 = 0.0f;
#pragma unroll
        for (int r = 0; r < 3; r++) {
            float a0 = mg[3 * r + 0], a1 = mg[3 * r + 1], a2 = mg[3 * r + 2];
            float b0 = mp[3 * r + 0], b1 = mp[3 * r + 1], b2 = mp[3 * r + 2];
            float e;
            e = a0 - b0; s1 = fmaf(e, e, s1);
            e = a1 - b1; s1 = fmaf(e, e, s1);
            e = a2 - b2; s1 = fmaf(e, e, s1);
            e = a0 + b0; s2 = fmaf(e, e, s2);
            e = a1 - b1; s2 = fmaf(e, e, s2);
            e = a2 + b2; s2 = fmaf(e, e, s2);
        }
        racc = fminf(sqrtf(s1), sqrtf(s2));
    }
    float invN = 1.0f / (float)N;
    float db = block_reduce_sum(dacc);
    if (threadIdx.x == 0) atomicAdd(out + 1, db * invN);
    float rb = block_reduce_sum(racc);
    if (threadIdx.x == 0) atomicAdd(out + 2, rb * invN);
}

// ---------------------------------------------------------------------------
// kernel_launch
//   d_in[0] confidence     (B,1,H,W)  f32  = 16,777,216
//   d_in[1] confidence_gt  (B,1,H,W)  f32
//   d_in[2] weight         (B,H,W)    f32
//   d_in[3] depth_and_rotation (N,5)  f32
//   d_in[4] ann_values     (N,5)      f32
//   d_in[5] ann_flags      (N,)       int32 (bool materialized as i32)
//   d_out: 3 f32 scalars
// ---------------------------------------------------------------------------
extern "C" void kernel_launch(void* const* d_in, const int* in_sizes, int n_in,
                              void* d_out, int out_size) {
    const float4* c = (const float4*)d_in[0];
    const float4* g = (const float4*)d_in[1];
    const float4* w = (const float4*)d_in[2];
    const float* dr = (const float*)d_in[3];
    const float* av = (const float*)d_in[4];
    const int*   fl = (const int*)d_in[5];
    float* out = (float*)d_out;

    int n  = in_sizes[0];      // 16,777,216
    int n4 = n >> 2;
    int N  = in_sizes[5];      // 8192

    zero_out_kernel<<<1, 32>>>(out);
    conf_loss_kernel<<<CONF_BLOCKS, THREADS>>>(c, g, w, out, n4);
    ann_loss_kernel<<<(N + THREADS - 1) / THREADS, THREADS>>>(dr, av, fl, out, N);
}

// round 3
// speedup vs baseline: 1.0511x; 1.0511x over previous
#include <cuda_runtime.h>

#define THREADS 256
#define CONF_BLOCKS 2048

// Persistent scratch for cross-block reduction (allocation-free rule:
// __device__ globals are the sanctioned scratch). Zero-initialized at module
// load; the last finishing block resets them so every graph replay starts
// from zero.
__device__ float g_scratch[3] = {0.0f, 0.0f, 0.0f};
__device__ unsigned int g_ticket = 0u;

// ---------------------------------------------------------------------------
// Block-level sum reduction: warp shuffle + one shared pass.
// ---------------------------------------------------------------------------
__device__ __forceinline__ float block_reduce_sum(float v) {
    __shared__ float s[32];
    int lane = threadIdx.x & 31;
    int wid  = threadIdx.x >> 5;
#pragma unroll
    for (int o = 16; o > 0; o >>= 1) v += __shfl_down_sync(0xffffffffu, v, o);
    if (lane == 0) s[wid] = v;
    __syncthreads();
    int nwarps = blockDim.x >> 5;
    v = (threadIdx.x < nwarps) ? s[lane] : 0.0f;
    if (wid == 0) {
#pragma unroll
        for (int o = 16; o > 0; o >>= 1) v += __shfl_down_sync(0xffffffffu, v, o);
    }
    __syncthreads();   // safe for reuse by subsequent calls
    return v;
}

// ---------------------------------------------------------------------------
// quat -> rotation matrix (row-major r[9]), matches reference quat2mat.
// ---------------------------------------------------------------------------
__device__ __forceinline__ void quat2mat(float q0, float q1, float q2, float q3,
                                         float* r) {
    float q00 = q0 * q0, q11 = q1 * q1, q22 = q2 * q2, q33 = q3 * q3;
    r[0] = q00 + q11 - q22 - q33;
    r[1] = 2.0f * (q1 * q2 - q0 * q3);
    r[2] = 2.0f * (q1 * q3 + q0 * q2);
    r[3] = 2.0f * (q1 * q2 + q0 * q3);
    r[4] = q00 - q11 + q22 - q33;
    r[5] = 2.0f * (q2 * q3 - q0 * q1);
    r[6] = 2.0f * (q1 * q3 - q0 * q2);
    r[7] = 2.0f * (q2 * q3 + q0 * q1);
    r[8] = q00 - q11 - q22 + q33;
}

// ---------------------------------------------------------------------------
// Fused kernel: all three losses in one launch.
//  out[0] = sum(weight*(conf-gt)^2) / 65536                (16.78M elems, HBM)
//  out[1] = sum(mask*(dr0-av0)^2) / N                      (N=8192, ALU)
//  out[2] = sum(mask*min(||Mg-Mp||F, ||Mg-Mp@RY||F)) / N
// Cross-block combine via device scratch + last-block-done; last block writes
// out[] with plain stores and resets scratch for the next graph replay.
// ---------------------------------------------------------------------------
__global__ void __launch_bounds__(THREADS)
fused_loss_kernel(const float4* __restrict__ c,
                  const float4* __restrict__ g,
                  const float4* __restrict__ w,
                  const float*  __restrict__ dr,
                  const float*  __restrict__ av,
                  const int*    __restrict__ flags,
                  float* __restrict__ out, int n4, int N) {
    int gtid = blockIdx.x * blockDim.x + threadIdx.x;
    int stride = gridDim.x * blockDim.x;

    // ---- annotation losses: one row per thread (first N global threads).
    // Issue these first so the tiny LDGs overlap the big streaming loads.
    float dacc = 0.0f, racc = 0.0f;
    if (gtid < N && flags[gtid] != 0) {
        const float* dri = dr + 5 * gtid;
        const float* avi = av + 5 * gtid;

        float dd = dri[0] - avi[0];
        dacc = dd * dd;

        float mp[9];
        quat2mat(avi[1], avi[2], avi[3], avi[4], mp);

        float q0 = dri[1], q1 = dri[2], q2 = dri[3], q3 = dri[4];
        float inv = rsqrtf(fmaf(q0, q0, fmaf(q1, q1, fmaf(q2, q2, q3 * q3))));
        // reference does q/||q|| then squares; rsqrtf error ~2e-7, fine at 1e-3
        float mg[9];
        quat2mat(q0 * inv, q1 * inv, q2 * inv, q3 * inv, mg);

        // RY = diag(-1,1,-1): m_pred @ RY negates columns 0 and 2.
        float s1 = 0.0f, s2 = 0.0f;
#pragma unroll
        for (int r = 0; r < 3; r++) {
            float a0 = mg[3 * r + 0], a1 = mg[3 * r + 1], a2 = mg[3 * r + 2];
            float b0 = mp[3 * r + 0], b1 = mp[3 * r + 1], b2 = mp[3 * r + 2];
            float e;
            e = a0 - b0; s1 = fmaf(e, e, s1);
            e = a1 - b1; s1 = fmaf(e, e, s1);
            e = a2 - b2; s1 = fmaf(e, e, s1);
            e = a0 + b0; s2 = fmaf(e, e, s2);
            e = a1 - b1; s2 = fmaf(e, e, s2);
            e = a2 + b2; s2 = fmaf(e, e, s2);
        }
        racc = fminf(sqrtf(s1), sqrtf(s2));
    }

    // ---- confidence loss: float4 grid-stride streaming reduction.
    float cacc = 0.0f;
    for (int i = gtid; i < n4; i += stride) {
        float4 cc = __ldg(c + i);
        float4 gg = __ldg(g + i);
        float4 ww = __ldg(w + i);
        float d;
        d = cc.x - gg.x; cacc = fmaf(ww.x * d, d, cacc);
        d = cc.y - gg.y; cacc = fmaf(ww.y * d, d, cacc);
        d = cc.z - gg.z; cacc = fmaf(ww.z * d, d, cacc);
        d = cc.w - gg.w; cacc = fmaf(ww.w * d, d, cacc);
    }

    // ---- block reduction of all three partials.
    float cb = block_reduce_sum(cacc);
    float db = block_reduce_sum(dacc);
    float rb = block_reduce_sum(racc);

    // ---- cross-block combine: scratch atomics + last-block-done.
    __shared__ bool is_last;
    if (threadIdx.x == 0) {
        float invN = 1.0f / (float)N;
        if (cb != 0.0f) atomicAdd(&g_scratch[0], cb * (1.0f / 65536.0f));
        if (db != 0.0f) atomicAdd(&g_scratch[1], db * invN);
        if (rb != 0.0f) atomicAdd(&g_scratch[2], rb * invN);
        __threadfence();
        unsigned int t = atomicAdd(&g_ticket, 1u);
        is_last = (t == (unsigned int)gridDim.x - 1u);
    }
    __syncthreads();

    if (is_last && threadIdx.x == 0) {
        // All prior blocks' atomics are visible (threadfence + ticket order).
        float r0 = *(volatile float*)&g_scratch[0];
        float r1 = *(volatile float*)&g_scratch[1];
        float r2 = *(volatile float*)&g_scratch[2];
        out[0] = r0;
        out[1] = r1;
        out[2] = r2;
        // Reset for next graph replay.
        g_scratch[0] = 0.0f;
        g_scratch[1] = 0.0f;
        g_scratch[2] = 0.0f;
        __threadfence();
        g_ticket = 0u;
    }
}

// ---------------------------------------------------------------------------
// kernel_launch
//   d_in[0] confidence     (B,1,H,W)  f32  = 16,777,216
//   d_in[1] confidence_gt  (B,1,H,W)  f32
//   d_in[2] weight         (B,H,W)    f32
//   d_in[3] depth_and_rotation (N,5)  f32
//   d_in[4] ann_values     (N,5)      f32
//   d_in[5] ann_flags      (N,)       int32 (bool materialized as i32)
//   d_out: 3 f32 scalars
// ---------------------------------------------------------------------------
extern "C" void kernel_launch(void* const* d_in, const int* in_sizes, int n_in,
                              void* d_out, int out_size) {
    const float4* c = (const float4*)d_in[0];
    const float4* g = (const float4*)d_in[1];
    const float4* w = (const float4*)d_in[2];
    const float* dr = (const float*)d_in[3];
    const float* av = (const float*)d_in[4];
    const int*   fl = (const int*)d_in[5];
    float* out = (float*)d_out;

    int n  = in_sizes[0];      // 16,777,216
    int n4 = n >> 2;
    int N  = in_sizes[5];      // 8192

    fused_loss_kernel<<<CONF_BLOCKS, THREADS>>>(c, g, w, dr, av, fl, out, n4, N);
}